// round 3
// baseline (speedup 1.0000x reference)
#include <cuda_runtime.h>

#define BATCH 8
#define NPOS  4096   // 64*64
#define KBITS 8
#define DV    32

// Scratch (allocation-free rule: __device__ globals)
__device__ unsigned char g_codes[BATCH * NPOS];
__device__ int           g_cnt[BATCH * 256];
__device__ float         g_table[BATCH * 256 * DV];   // normalized Acc/Z

// ---------------------------------------------------------------------------
// Kernel 0: zero histograms (must be re-zeroed every replay)
// ---------------------------------------------------------------------------
__global__ void k_zero()
{
    int i = blockIdx.x * blockDim.x + threadIdx.x;
    if (i < BATCH * 256) g_cnt[i] = 0;
}

// ---------------------------------------------------------------------------
// Kernel 1: bitpack z -> 8-bit codes + per-batch 256-bin histogram
// grid = BATCH*16 blocks x 256 threads; block covers 256 consecutive n
// ---------------------------------------------------------------------------
__global__ void k_pack(const float* __restrict__ z)
{
    __shared__ int hist[256];
    const int tid = threadIdx.x;
    hist[tid] = 0;
    __syncthreads();

    const int b = blockIdx.x >> 4;
    const int n = ((blockIdx.x & 15) << 8) | tid;

    const float* zb = z + (size_t)b * KBITS * NPOS + n;
    int code = 0;
#pragma unroll
    for (int k = 0; k < KBITS; k++)
        code |= (zb[(size_t)k * NPOS] > 0.5f) ? (1 << k) : 0;

    g_codes[b * NPOS + n] = (unsigned char)code;
    atomicAdd(&hist[code], 1);
    __syncthreads();

    const int h = hist[tid];
    if (h) atomicAdd(&g_cnt[b * 256 + tid], h);
}

// ---------------------------------------------------------------------------
// Kernel 2: build normalized value table per (batch, query-code)
//   table[b][q][d] = (sum_c cnt[c]*w[pop(q^c)]*E[c][d]) / (sum_c cnt[c]*w[pop(q^c)])
// grid = BATCH*32 blocks x 256 threads; warp handles one q, lane = dim d
// wc is warp-uniform; E loads and table stores are coalesced across lanes.
// ---------------------------------------------------------------------------
__global__ void k_table(const float* __restrict__ vemb,
                        const float* __restrict__ temp)
{
    __shared__ float cnt_s[256];
    __shared__ float w_s[9];

    const int tid = threadIdx.x;
    const int b   = blockIdx.x >> 5;

    if (tid < 9) {
        float t = fmaxf(*temp, 0.1f);
        w_s[tid] = expf(-(float)tid / t);
    }
    cnt_s[tid] = (float)g_cnt[b * 256 + tid];
    __syncthreads();

    const int warp = tid >> 5;
    const int lane = tid & 31;
    const int q    = ((blockIdx.x & 31) << 3) | warp;

    float acc  = 0.0f;
    float zsum = 0.0f;
#pragma unroll 8
    for (int c = 0; c < 256; c++) {
        const float wc = cnt_s[c] * w_s[__popc(q ^ c)];
        zsum += wc;
        acc  += wc * __ldg(vemb + c * DV + lane);
    }
    g_table[((b << 8) | q) * DV + lane] = acc / zsum;
}

// ---------------------------------------------------------------------------
// Kernel 3: scatter output  out[b][d][n] = table[b][codes[b][n]][d]
// grid = BATCH*16 blocks x 256 threads; thread per (b,n), loop d.
// Stores coalesced (n contiguous across lanes); table rows are L1-resident.
// ---------------------------------------------------------------------------
__global__ void k_out(float* __restrict__ out)
{
    const int b = blockIdx.x >> 4;
    const int n = ((blockIdx.x & 15) << 8) | threadIdx.x;

    const int code = g_codes[b * NPOS + n];
    const float* __restrict__ trow = g_table + ((b << 8) | code) * DV;
    float* __restrict__ ob = out + (size_t)b * DV * NPOS + n;

#pragma unroll
    for (int d = 0; d < DV; d++)
        ob[(size_t)d * NPOS] = __ldg(trow + d);
}

// ---------------------------------------------------------------------------
extern "C" void kernel_launch(void* const* d_in, const int* in_sizes, int n_in,
                              void* d_out, int out_size)
{
    const float* z    = (const float*)d_in[0];   // (8,8,64,64) f32
    const float* temp = (const float*)d_in[1];   // scalar f32
    const float* vemb = (const float*)d_in[2];   // (256,32) f32
    float*       out  = (float*)d_out;           // (8,32,64,64) f32

    k_zero <<<8,   256>>>();
    k_pack <<<BATCH * 16, 256>>>(z);
    k_table<<<BATCH * 32, 256>>>(vemb, temp);
    k_out  <<<BATCH * 16, 256>>>(out);
}

// round 4
// speedup vs baseline: 1.0137x; 1.0137x over previous
#include <cuda_runtime.h>

#define BATCH 8
#define NPOS  4096   // 64*64
#define KBITS 8
#define DV    32
#define NTILES 16    // k_pack blocks per batch (256 positions each)

// Scratch (allocation-free rule: __device__ globals)
__device__ unsigned char g_codes[BATCH * NPOS];
__device__ int           g_part[BATCH * NTILES * 256];   // per-block partial hists
__device__ float         g_table[BATCH * 256 * DV];      // normalized Acc/Z

// ---------------------------------------------------------------------------
// Kernel 1: bitpack z -> 8-bit codes + per-block partial 256-bin histogram.
// Every g_part slot is written unconditionally every run -> no zeroing kernel,
// no global atomics.
// grid = BATCH*NTILES blocks x 256 threads; block covers 256 consecutive n.
// ---------------------------------------------------------------------------
__global__ void k_pack(const float* __restrict__ z)
{
    __shared__ int hist[256];
    const int tid = threadIdx.x;
    hist[tid] = 0;
    __syncthreads();

    const int b = blockIdx.x >> 4;
    const int t = blockIdx.x & (NTILES - 1);
    const int n = (t << 8) | tid;

    const float* zb = z + (size_t)b * KBITS * NPOS + n;
    int code = 0;
#pragma unroll
    for (int k = 0; k < KBITS; k++)
        code |= (zb[(size_t)k * NPOS] > 0.5f) ? (1 << k) : 0;

    g_codes[b * NPOS + n] = (unsigned char)code;
    atomicAdd(&hist[code], 1);
    __syncthreads();

    g_part[(b * NTILES + t) * 256 + tid] = hist[tid];
}

// ---------------------------------------------------------------------------
// Kernel 2: build normalized value table per (batch, query-code)
//   table[b][q][d] = (sum_c cnt[c]*w[pop(q^c)]*E[c][d]) / (sum_c cnt[c]*w[pop(q^c)])
// grid = BATCH*32 blocks x 256 threads; warp handles one q, lane = dim d.
// ---------------------------------------------------------------------------
__global__ void k_table(const float* __restrict__ vemb,
                        const float* __restrict__ temp)
{
    __shared__ float cnt_s[256];
    __shared__ float w_s[9];

    const int tid = threadIdx.x;
    const int b   = blockIdx.x >> 5;

    if (tid < 9) {
        float t = fmaxf(*temp, 0.1f);
        w_s[tid] = expf(-(float)tid / t);
    }
    // sum the 16 partial histograms (coalesced per slice)
    int cnt = 0;
#pragma unroll
    for (int t = 0; t < NTILES; t++)
        cnt += g_part[(b * NTILES + t) * 256 + tid];
    cnt_s[tid] = (float)cnt;
    __syncthreads();

    const int warp = tid >> 5;
    const int lane = tid & 31;
    const int q    = ((blockIdx.x & 31) << 3) | warp;

    float acc  = 0.0f;
    float zsum = 0.0f;
#pragma unroll 8
    for (int c = 0; c < 256; c++) {
        const float wc = cnt_s[c] * w_s[__popc(q ^ c)];
        zsum += wc;
        acc  += wc * __ldg(vemb + c * DV + lane);
    }
    g_table[((b << 8) | q) * DV + lane] = acc / zsum;
}

// ---------------------------------------------------------------------------
// Kernel 3: scatter output  out[b][d][n] = table[b][codes[b][n]][d]
// Thread per (b, d, n-quad): one uchar4 code load, 4 independent L1 table
// gathers, one float4 store. 262144 threads / 1024 blocks -> high occupancy,
// vectorized coalesced stores.
// ---------------------------------------------------------------------------
__global__ void k_out(float* __restrict__ out)
{
    const int id = blockIdx.x * 256 + threadIdx.x;   // 0 .. 262143
    const int n4 = id & 1023;          // quad index within batch (n = n4*4)
    const int d  = (id >> 10) & 31;
    const int b  = id >> 15;

    const uchar4 c = *(const uchar4*)(g_codes + b * NPOS + n4 * 4);
    const float* __restrict__ tb = g_table + (b << 13);   // b*256*32

    float4 v;
    v.x = __ldg(tb + c.x * DV + d);
    v.y = __ldg(tb + c.y * DV + d);
    v.z = __ldg(tb + c.z * DV + d);
    v.w = __ldg(tb + c.w * DV + d);

    *(float4*)(out + (((size_t)b * DV + d) << 12) + n4 * 4) = v;
}

// ---------------------------------------------------------------------------
extern "C" void kernel_launch(void* const* d_in, const int* in_sizes, int n_in,
                              void* d_out, int out_size)
{
    const float* z    = (const float*)d_in[0];   // (8,8,64,64) f32
    const float* temp = (const float*)d_in[1];   // scalar f32
    const float* vemb = (const float*)d_in[2];   // (256,32) f32
    float*       out  = (float*)d_out;           // (8,32,64,64) f32

    k_pack <<<BATCH * NTILES, 256>>>(z);
    k_table<<<BATCH * 32,    256>>>(vemb, temp);
    k_out  <<<BATCH * DV * NPOS / 4 / 256, 256>>>(out);
}